// round 15
// baseline (speedup 1.0000x reference)
#include <cuda_runtime.h>
#include <cuda_bf16.h>

// R15: chunked split pipeline (CHUNK=4, h stays L2-resident) +
//  B reads conv2 weights from smem as pre-paired float2 (broadcast LDS.64,
//  floor 2cyc) instead of per-iteration constant loads (LDC floor 8cyc).

#define HH 512
#define WW 512
#define HWS (HH * WW)
#define CHUNK 4

__constant__ float c_w1[432];    // (16,3,3,3)
__constant__ float c_b1[16];
__constant__ float c_w2[2592];   // (18,16,3,3)
__constant__ float c_b2[18];
__constant__ float c_wt[9];

// intermediate h for one chunk: [z][ci][y][x] — 67 MB, fits L2 (126 MB)
__device__ float g_h[CHUNK * 16 * HWS];

// B smem layout: [ s_w2: 1296 float2 (10368 B) | s_h: 16*18*36 floats (41472 B) ]
#define SW2_F2   1296
#define SH_BASE  (SW2_F2 * 2)              // float offset of s_h
#define SMEM_B_BYTES (SW2_F2 * 8 + 16 * 18 * 36 * 4)   // 51840

// exact GELU via Abramowitz-Stegun 7.1.26 erf (|abs err| <= 1.5e-7)
__device__ __forceinline__ float gelu_fast(float x) {
    float z = 0.70710678118f * x;
    float a = fabsf(z);
    float t = __fdividef(1.0f, fmaf(0.3275911f, a, 1.0f));
    float p = fmaf(1.061405429f, t, -1.453152027f);
    p = fmaf(p, t, 1.421413741f);
    p = fmaf(p, t, -0.284496736f);
    p = fmaf(p, t, 0.254829592f);
    p = p * t;
    float e = __expf(-a * a);
    float erfa = fmaf(-p, e, 1.0f);
    float erfz = copysignf(erfa, z);
    return x * (0.5f * (1.0f + erfz));
}

// ---------------- Kernel A: conv1 + GELU, 2 px/thread, 1 row/block ----------
__global__ __launch_bounds__(256)
void conv1_gelu_kernel(const float* __restrict__ wind,
                       const float* __restrict__ topo,
                       int b0) {
    const int z   = blockIdx.z;               // batch within chunk
    const int b   = b0 + z;
    const int y   = blockIdx.y;
    const int gx0 = threadIdx.x * 2;          // 0..510

    const float* src[3];
    src[0] = wind + (size_t)b * 2 * HWS;
    src[1] = src[0] + HWS;
    src[2] = topo + (size_t)b * HWS;

    const bool ml = gx0 > 0;
    const bool mr = gx0 + 2 < WW;
    const int  xl = max(gx0 - 1, 0);
    const int  xr = min(gx0 + 2, WW - 1);

    float in_reg[3][3][4];
    #pragma unroll
    for (int c = 0; c < 3; c++) {
        #pragma unroll
        for (int r = 0; r < 3; r++) {
            int ry = y - 1 + r;
            bool rok = (unsigned)ry < HH;
            const float* row = src[c] + min(max(ry, 0), HH - 1) * WW;
            float a = row[xl];
            float2 m = *(const float2*)&row[gx0];
            float d = row[xr];
            in_reg[c][r][0] = (rok && ml) ? a   : 0.f;
            in_reg[c][r][1] = rok         ? m.x : 0.f;
            in_reg[c][r][2] = rok         ? m.y : 0.f;
            in_reg[c][r][3] = (rok && mr) ? d   : 0.f;
        }
    }

    float* hb = g_h + (size_t)z * 16 * HWS + (size_t)y * WW + gx0;
    #pragma unroll
    for (int o = 0; o < 16; o++) {
        float a0 = c_b1[o], a1 = a0;
        #pragma unroll
        for (int c = 0; c < 3; c++)
            #pragma unroll
            for (int r = 0; r < 3; r++)
                #pragma unroll
                for (int kx = 0; kx < 3; kx++) {
                    const float w = c_w1[o * 27 + (c * 3 + r) * 3 + kx];
                    a0 = fmaf(in_reg[c][r][kx],     w, a0);
                    a1 = fmaf(in_reg[c][r][kx + 1], w, a1);
                }
        *(float2*)&hb[(size_t)o * HWS] = make_float2(gelu_fast(a0), gelu_fast(a1));
    }
}

// ---------------- Kernel B: smem tile + smem weights + bilinear -------------
// s_h[ci][hy][x] : x = 0..33 corresponds to global columns tx0-1 .. tx0+32.
// s_w2[k*144 + i] = (w2[(2k)*144 + i], w2[(2k+1)*144 + i])  i = ci*9+ky*3+kx
__global__ __launch_bounds__(256)
void deform_kernel(const float* __restrict__ pm25,
                   float* __restrict__ out,
                   int b0) {
    extern __shared__ float smem[];
    float2* s_w2 = (float2*)smem;
    float*  s_hb = smem + SH_BASE;
    #define SH(ci, hy, x) s_hb[((ci) * 18 + (hy)) * 36 + (x)]

    const int tid = threadIdx.x;
    const int z   = blockIdx.z;
    const int b   = b0 + z;
    const int ty0 = blockIdx.y * 16;
    const int tx0 = blockIdx.x * 32;
    const float* hb = g_h + (size_t)z * 16 * HWS;

    // ---- copy paired conv2 weights into smem (one-time LDC) ----
    for (int j = tid; j < SW2_F2; j += 256) {
        int k = j / 144;
        int i = j - k * 144;
        s_w2[j] = make_float2(c_w2[(2 * k) * 144 + i], c_w2[(2 * k + 1) * 144 + i]);
    }

    // ---- main tile: per (ci,hy) row, 8 aligned LDG.128 at tx0+4q, stored
    // as 4 scalar STS into x = 4q+1..4q+4 (odd shift). 2304 items.
    for (int j = tid; j < 2304; j += 256) {
        int row = j >> 3;                 // ci*18 + hy
        int q   = j & 7;
        int ci  = row / 18;
        int hy  = row - ci * 18;
        int gy  = ty0 - 1 + hy;
        float4 v = make_float4(0.f, 0.f, 0.f, 0.f);
        if ((unsigned)gy < HH)
            v = *(const float4*)(hb + (size_t)ci * HWS + (size_t)gy * WW + tx0 + q * 4);
        float* d = &SH(ci, hy, q * 4 + 1);
        d[0] = v.x; d[1] = v.y; d[2] = v.z; d[3] = v.w;
    }
    // ---- halo columns: x=0 (global tx0-1) and x=33 (global tx0+32) ----
    for (int j = tid; j < 576; j += 256) {
        int side = (j >= 288);
        int r    = j - side * 288;
        int ci   = r / 18;
        int hy   = r - ci * 18;
        int gy   = ty0 - 1 + hy;
        int gx   = side ? (tx0 + 32) : (tx0 - 1);
        float v = 0.f;
        if ((unsigned)gy < HH && (unsigned)gx < WW)
            v = hb[(size_t)ci * HWS + (size_t)gy * WW + gx];
        SH(ci, hy, side ? 33 : 0) = v;
    }
    __syncthreads();

    // ---- stage 2: 2px/thread, weights via broadcast LDS.64 ----
    const int py  = tid >> 4;            // 0..15
    const int px2 = (tid & 15) * 2;      // 0..30
    const int gy  = ty0 + py;
    const int gx0 = tx0 + px2;
    const float* pimg = pm25 + (size_t)b * HWS;

    float out0 = 0.f, out1 = 0.f;
    #pragma unroll 1
    for (int k = 0; k < 9; k++) {
        float wk = c_wt[k];
        if (wk == 0.f) continue;         // warp-uniform skip

        float dy0 = c_b2[2 * k],     dy1 = dy0;
        float dx0 = c_b2[2 * k + 1], dx1 = dx0;
        const float2* wp = s_w2 + k * 144;
        #pragma unroll
        for (int ky = 0; ky < 3; ky++) {
            #pragma unroll
            for (int ci = 0; ci < 16; ci++) {
                // x=px2..px2+3 <-> global gx0-1..gx0+2, both loads 8B-aligned
                const float2 a = *(const float2*)&SH(ci, py + ky, px2);
                const float2 c = *(const float2*)&SH(ci, py + ky, px2 + 2);
                const int wi = ci * 9 + ky * 3;
                const float2 w0 = wp[wi];        // (wy0, wx0) broadcast
                const float2 w1 = wp[wi + 1];
                const float2 w2 = wp[wi + 2];
                dy0 = fmaf(a.x, w0.x, dy0); dy0 = fmaf(a.y, w1.x, dy0); dy0 = fmaf(c.x, w2.x, dy0);
                dy1 = fmaf(a.y, w0.x, dy1); dy1 = fmaf(c.x, w1.x, dy1); dy1 = fmaf(c.y, w2.x, dy1);
                dx0 = fmaf(a.x, w0.y, dx0); dx0 = fmaf(a.y, w1.y, dx0); dx0 = fmaf(c.x, w2.y, dx0);
                dx1 = fmaf(a.y, w0.y, dx1); dx1 = fmaf(c.x, w1.y, dx1); dx1 = fmaf(c.y, w2.y, dx1);
            }
        }

        const float kyo = (float)(k / 3 - 1);
        const float kxo = (float)(k % 3 - 1);
        #pragma unroll
        for (int px = 0; px < 2; px++) {
            float dyv = px ? dy1 : dy0;
            float dxv = px ? dx1 : dx0;
            float py_ = (float)gy + kyo + dyv;
            float px_ = (float)(gx0 + px) + kxo + dxv;
            float y0f = floorf(py_), x0f = floorf(px_);
            float wy = py_ - y0f, wx = px_ - x0f;
            int y0 = (int)y0f, x0 = (int)x0f;
            int y1 = y0 + 1,   x1 = x0 + 1;
            bool vy0 = (unsigned)y0 < HH, vy1 = (unsigned)y1 < HH;
            bool vx0 = (unsigned)x0 < WW, vx1 = (unsigned)x1 < WW;
            int yc0 = min(max(y0, 0), HH - 1), yc1 = min(max(y1, 0), HH - 1);
            int xc0 = min(max(x0, 0), WW - 1), xc1 = min(max(x1, 0), WW - 1);
            const float* r0 = pimg + yc0 * WW;
            const float* r1 = pimg + yc1 * WW;
            float v00 = (vy0 && vx0) ? r0[xc0] : 0.f;
            float v01 = (vy0 && vx1) ? r0[xc1] : 0.f;
            float v10 = (vy1 && vx0) ? r1[xc0] : 0.f;
            float v11 = (vy1 && vx1) ? r1[xc1] : 0.f;
            float samp = (1.f - wy) * (1.f - wx) * v00
                       + (1.f - wy) * wx         * v01
                       + wy         * (1.f - wx) * v10
                       + wy         * wx         * v11;
            if (px) out1 = fmaf(samp, wk, out1);
            else    out0 = fmaf(samp, wk, out0);
        }
    }

    *(float2*)&out[(size_t)b * HWS + (size_t)gy * WW + gx0] = make_float2(out0, out1);
}

extern "C" void kernel_launch(void* const* d_in, const int* in_sizes, int n_in,
                              void* d_out, int out_size) {
    const float* pm25 = (const float*)d_in[0];
    const float* wind = (const float*)d_in[1];
    const float* topo = (const float*)d_in[2];

    cudaFuncSetAttribute(deform_kernel,
                         cudaFuncAttributeMaxDynamicSharedMemorySize, SMEM_B_BYTES);

    cudaMemcpyToSymbolAsync(c_w1, d_in[3], 432  * sizeof(float), 0, cudaMemcpyDeviceToDevice);
    cudaMemcpyToSymbolAsync(c_b1, d_in[4], 16   * sizeof(float), 0, cudaMemcpyDeviceToDevice);
    cudaMemcpyToSymbolAsync(c_w2, d_in[5], 2592 * sizeof(float), 0, cudaMemcpyDeviceToDevice);
    cudaMemcpyToSymbolAsync(c_b2, d_in[6], 18   * sizeof(float), 0, cudaMemcpyDeviceToDevice);
    cudaMemcpyToSymbolAsync(c_wt, d_in[7], 9    * sizeof(float), 0, cudaMemcpyDeviceToDevice);

    float* out = (float*)d_out;
    int B = in_sizes[0] / (HH * WW);

    for (int b0 = 0; b0 < B; b0 += CHUNK) {
        int nz = (B - b0 < CHUNK) ? (B - b0) : CHUNK;
        dim3 gridA(1, HH, nz);               // one 512-px row per block
        conv1_gelu_kernel<<<gridA, 256>>>(wind, topo, b0);
        dim3 gridB(WW / 32, HH / 16, nz);    // 32x16 tile, 2 px/thread
        deform_kernel<<<gridB, 256, SMEM_B_BYTES>>>(pm25, out, b0);
    }
}

// round 16
// speedup vs baseline: 1.3710x; 1.3710x over previous
#include <cuda_runtime.h>
#include <cuda_fp16.h>

// R16: split pipeline, h stored as FP16 (67MB, fits L2 for ALL 8 batches).
//  A: conv1(3->16,3x3,pad1)+exact GELU -> g_h[b][ci][y][x] (half), 1 launch.
//  B: R13-proven deform kernel (smem fp32 tile, halo baked into origin,
//     LDC weights), 1 big 4096-block launch; copy converts half->float.

#define HH 512
#define WW 512
#define HWS (HH * WW)
#define BMAX 8

__constant__ float c_w1[432];    // (16,3,3,3)
__constant__ float c_b1[16];
__constant__ float c_w2[2592];   // (18,16,3,3)
__constant__ float c_b2[18];
__constant__ float c_wt[9];

// intermediate h (fp16), channel-plane major: [b][ci][y][x] — 67 MB total
__device__ __half g_h[BMAX * 16 * HWS];

// exact GELU via Abramowitz-Stegun 7.1.26 erf (|abs err| <= 1.5e-7)
__device__ __forceinline__ float gelu_fast(float x) {
    float z = 0.70710678118f * x;
    float a = fabsf(z);
    float t = __fdividef(1.0f, fmaf(0.3275911f, a, 1.0f));
    float p = fmaf(1.061405429f, t, -1.453152027f);
    p = fmaf(p, t, 1.421413741f);
    p = fmaf(p, t, -0.284496736f);
    p = fmaf(p, t, 0.254829592f);
    p = p * t;
    float e = __expf(-a * a);
    float erfa = fmaf(-p, e, 1.0f);
    float erfz = copysignf(erfa, z);
    return x * (0.5f * (1.0f + erfz));
}

// ---------------- Kernel A: conv1 + GELU, 2 px/thread, 1 row/block ----------
__global__ __launch_bounds__(256)
void conv1_gelu_kernel(const float* __restrict__ wind,
                       const float* __restrict__ topo) {
    const int b   = blockIdx.z;
    const int y   = blockIdx.y;
    const int gx0 = threadIdx.x * 2;          // 0..510

    const float* src[3];
    src[0] = wind + (size_t)b * 2 * HWS;
    src[1] = src[0] + HWS;
    src[2] = topo + (size_t)b * HWS;

    const bool ml = gx0 > 0;
    const bool mr = gx0 + 2 < WW;
    const int  xl = max(gx0 - 1, 0);
    const int  xr = min(gx0 + 2, WW - 1);

    float in_reg[3][3][4];
    #pragma unroll
    for (int c = 0; c < 3; c++) {
        #pragma unroll
        for (int r = 0; r < 3; r++) {
            int ry = y - 1 + r;
            bool rok = (unsigned)ry < HH;
            const float* row = src[c] + min(max(ry, 0), HH - 1) * WW;
            float a = row[xl];
            float2 m = *(const float2*)&row[gx0];
            float d = row[xr];
            in_reg[c][r][0] = (rok && ml) ? a   : 0.f;
            in_reg[c][r][1] = rok         ? m.x : 0.f;
            in_reg[c][r][2] = rok         ? m.y : 0.f;
            in_reg[c][r][3] = (rok && mr) ? d   : 0.f;
        }
    }

    __half* hb = g_h + (size_t)b * 16 * HWS + (size_t)y * WW + gx0;
    #pragma unroll
    for (int o = 0; o < 16; o++) {
        float a0 = c_b1[o], a1 = a0;
        #pragma unroll
        for (int c = 0; c < 3; c++)
            #pragma unroll
            for (int r = 0; r < 3; r++)
                #pragma unroll
                for (int kx = 0; kx < 3; kx++) {
                    const float w = c_w1[o * 27 + (c * 3 + r) * 3 + kx];
                    a0 = fmaf(in_reg[c][r][kx],     w, a0);
                    a1 = fmaf(in_reg[c][r][kx + 1], w, a1);
                }
        *(__half2*)&hb[(size_t)o * HWS] =
            __floats2half2_rn(gelu_fast(a0), gelu_fast(a1));
    }
}

// ---------------- Kernel B: smem tile + conv2 per tap + bilinear ------------
// s_h[ci][hy][x] : x = 0..33 corresponds to global columns tx0-1 .. tx0+32.
__global__ __launch_bounds__(256, 4)
void deform_kernel(const float* __restrict__ pm25,
                   float* __restrict__ out) {
    __shared__ float s_h[16][18][36];   // 41472 B

    const int tid = threadIdx.x;
    const int b   = blockIdx.z;
    const int ty0 = blockIdx.y * 16;
    const int tx0 = blockIdx.x * 32;
    const __half* hb = g_h + (size_t)b * 16 * HWS;

    // ---- main tile: per (ci,hy) row, 8 x (LDG.64 of 4 halves -> cvt ->
    // 4 scalar STS into x = 4q+1..4q+4). 2304 items.
    for (int j = tid; j < 2304; j += 256) {
        int row = j >> 3;                 // ci*18 + hy
        int q   = j & 7;
        int ci  = row / 18;
        int hy  = row - ci * 18;
        int gy  = ty0 - 1 + hy;
        float4 v = make_float4(0.f, 0.f, 0.f, 0.f);
        if ((unsigned)gy < HH) {
            const __half2* p = (const __half2*)(hb + (size_t)ci * HWS
                                                   + (size_t)gy * WW + tx0 + q * 4);
            __half2 h01 = p[0];
            __half2 h23 = p[1];
            float2 f01 = __half22float2(h01);
            float2 f23 = __half22float2(h23);
            v = make_float4(f01.x, f01.y, f23.x, f23.y);
        }
        float* d = &s_h[ci][hy][q * 4 + 1];
        d[0] = v.x; d[1] = v.y; d[2] = v.z; d[3] = v.w;
    }
    // ---- halo columns: x=0 (global tx0-1) and x=33 (global tx0+32) ----
    for (int j = tid; j < 576; j += 256) {
        int side = (j >= 288);
        int r    = j - side * 288;
        int ci   = r / 18;
        int hy   = r - ci * 18;
        int gy   = ty0 - 1 + hy;
        int gx   = side ? (tx0 + 32) : (tx0 - 1);
        float v = 0.f;
        if ((unsigned)gy < HH && (unsigned)gx < WW)
            v = __half2float(hb[(size_t)ci * HWS + (size_t)gy * WW + gx]);
        s_h[ci][hy][side ? 33 : 0] = v;
    }
    __syncthreads();

    // ---- stage 2: R13-exact 2px/thread pattern ----
    const int py  = tid >> 4;            // 0..15
    const int px2 = (tid & 15) * 2;      // 0..30
    const int gy  = ty0 + py;
    const int gx0 = tx0 + px2;
    const float* pimg = pm25 + (size_t)b * HWS;

    float out0 = 0.f, out1 = 0.f;
    #pragma unroll 1
    for (int k = 0; k < 9; k++) {
        float wk = c_wt[k];
        if (wk == 0.f) continue;         // warp-uniform skip

        float dy0 = c_b2[2 * k],     dy1 = dy0;
        float dx0 = c_b2[2 * k + 1], dx1 = dx0;
        const int wbase_y = (2 * k) * 144;
        const int wbase_x = (2 * k + 1) * 144;
        #pragma unroll
        for (int ky = 0; ky < 3; ky++) {
            #pragma unroll
            for (int ci = 0; ci < 16; ci++) {
                // x=px2..px2+3 <-> global gx0-1..gx0+2, both loads 8B-aligned
                const float2 a = *(const float2*)&s_h[ci][py + ky][px2];
                const float2 c = *(const float2*)&s_h[ci][py + ky][px2 + 2];
                const int wi = ci * 9 + ky * 3;
                float wy0 = c_w2[wbase_y + wi + 0];
                float wy1 = c_w2[wbase_y + wi + 1];
                float wy2 = c_w2[wbase_y + wi + 2];
                float wx0 = c_w2[wbase_x + wi + 0];
                float wx1 = c_w2[wbase_x + wi + 1];
                float wx2 = c_w2[wbase_x + wi + 2];
                dy0 = fmaf(a.x, wy0, dy0); dy0 = fmaf(a.y, wy1, dy0); dy0 = fmaf(c.x, wy2, dy0);
                dy1 = fmaf(a.y, wy0, dy1); dy1 = fmaf(c.x, wy1, dy1); dy1 = fmaf(c.y, wy2, dy1);
                dx0 = fmaf(a.x, wx0, dx0); dx0 = fmaf(a.y, wx1, dx0); dx0 = fmaf(c.x, wx2, dx0);
                dx1 = fmaf(a.y, wx0, dx1); dx1 = fmaf(c.x, wx1, dx1); dx1 = fmaf(c.y, wx2, dx1);
            }
        }

        const float kyo = (float)(k / 3 - 1);
        const float kxo = (float)(k % 3 - 1);
        #pragma unroll
        for (int px = 0; px < 2; px++) {
            float dyv = px ? dy1 : dy0;
            float dxv = px ? dx1 : dx0;
            float py_ = (float)gy + kyo + dyv;
            float px_ = (float)(gx0 + px) + kxo + dxv;
            float y0f = floorf(py_), x0f = floorf(px_);
            float wy = py_ - y0f, wx = px_ - x0f;
            int y0 = (int)y0f, x0 = (int)x0f;
            int y1 = y0 + 1,   x1 = x0 + 1;
            bool vy0 = (unsigned)y0 < HH, vy1 = (unsigned)y1 < HH;
            bool vx0 = (unsigned)x0 < WW, vx1 = (unsigned)x1 < WW;
            int yc0 = min(max(y0, 0), HH - 1), yc1 = min(max(y1, 0), HH - 1);
            int xc0 = min(max(x0, 0), WW - 1), xc1 = min(max(x1, 0), WW - 1);
            const float* r0 = pimg + yc0 * WW;
            const float* r1 = pimg + yc1 * WW;
            float v00 = (vy0 && vx0) ? r0[xc0] : 0.f;
            float v01 = (vy0 && vx1) ? r0[xc1] : 0.f;
            float v10 = (vy1 && vx0) ? r1[xc0] : 0.f;
            float v11 = (vy1 && vx1) ? r1[xc1] : 0.f;
            float samp = (1.f - wy) * (1.f - wx) * v00
                       + (1.f - wy) * wx         * v01
                       + wy         * (1.f - wx) * v10
                       + wy         * wx         * v11;
            if (px) out1 = fmaf(samp, wk, out1);
            else    out0 = fmaf(samp, wk, out0);
        }
    }

    *(float2*)&out[(size_t)b * HWS + (size_t)gy * WW + gx0] = make_float2(out0, out1);
}

extern "C" void kernel_launch(void* const* d_in, const int* in_sizes, int n_in,
                              void* d_out, int out_size) {
    const float* pm25 = (const float*)d_in[0];
    const float* wind = (const float*)d_in[1];
    const float* topo = (const float*)d_in[2];

    cudaMemcpyToSymbolAsync(c_w1, d_in[3], 432  * sizeof(float), 0, cudaMemcpyDeviceToDevice);
    cudaMemcpyToSymbolAsync(c_b1, d_in[4], 16   * sizeof(float), 0, cudaMemcpyDeviceToDevice);
    cudaMemcpyToSymbolAsync(c_w2, d_in[5], 2592 * sizeof(float), 0, cudaMemcpyDeviceToDevice);
    cudaMemcpyToSymbolAsync(c_b2, d_in[6], 18   * sizeof(float), 0, cudaMemcpyDeviceToDevice);
    cudaMemcpyToSymbolAsync(c_wt, d_in[7], 9    * sizeof(float), 0, cudaMemcpyDeviceToDevice);

    float* out = (float*)d_out;
    int B = in_sizes[0] / (HH * WW);

    dim3 gridA(1, HH, B);              // all batches, one launch
    conv1_gelu_kernel<<<gridA, 256>>>(wind, topo);

    dim3 gridB(WW / 32, HH / 16, B);   // all batches, one launch, 7 waves
    deform_kernel<<<gridB, 256>>>(pm25, out);
}

// round 17
// speedup vs baseline: 1.5614x; 1.1388x over previous
#include <cuda_runtime.h>
#include <cuda_fp16.h>

// R17: split pipeline, h stored FP16 CHANNEL-LAST with padded zero columns:
//   g_h[b][y][x'][ci], x' = col+1 (x'=0 and x'=513 are zero) -> B needs no
//   column guards and no shared-memory staging at all.
//  A: conv1+GELU, one launch, 4x STG.128 per thread.
//  B: conv2 per nonzero tap straight from (L2-resident) g_h + bilinear.

#define HH 512
#define WW 512
#define HWS (HH * WW)
#define XP 514            // padded x' dimension
#define BMAX 8

__constant__ float c_w1[432];    // (16,3,3,3)
__constant__ float c_b1[16];
__constant__ float c_w2[2592];   // (18,16,3,3)
__constant__ float c_b2[18];
__constant__ float c_wt[9];

// h, channel-last fp16: [b][y][x'][ci] — 67.4 MB, fits L2
__device__ __half g_h[(size_t)BMAX * HH * XP * 16];

// exact GELU via Abramowitz-Stegun 7.1.26 erf (|abs err| <= 1.5e-7)
__device__ __forceinline__ float gelu_fast(float x) {
    float z = 0.70710678118f * x;
    float a = fabsf(z);
    float t = __fdividef(1.0f, fmaf(0.3275911f, a, 1.0f));
    float p = fmaf(1.061405429f, t, -1.453152027f);
    p = fmaf(p, t, 1.421413741f);
    p = fmaf(p, t, -0.284496736f);
    p = fmaf(p, t, 0.254829592f);
    p = p * t;
    float e = __expf(-a * a);
    float erfa = fmaf(-p, e, 1.0f);
    float erfz = copysignf(erfa, z);
    return x * (0.5f * (1.0f + erfz));
}

// ---------------- Kernel A: conv1 + GELU, 2 px/thread, 1 row/block ----------
__global__ __launch_bounds__(256)
void conv1_gelu_kernel(const float* __restrict__ wind,
                       const float* __restrict__ topo) {
    const int b   = blockIdx.z;
    const int y   = blockIdx.y;
    const int gx0 = threadIdx.x * 2;          // 0..510

    const float* src[3];
    src[0] = wind + (size_t)b * 2 * HWS;
    src[1] = src[0] + HWS;
    src[2] = topo + (size_t)b * HWS;

    const bool ml = gx0 > 0;
    const bool mr = gx0 + 2 < WW;
    const int  xl = max(gx0 - 1, 0);
    const int  xr = min(gx0 + 2, WW - 1);

    float in_reg[3][3][4];
    #pragma unroll
    for (int c = 0; c < 3; c++) {
        #pragma unroll
        for (int r = 0; r < 3; r++) {
            int ry = y - 1 + r;
            bool rok = (unsigned)ry < HH;
            const float* row = src[c] + min(max(ry, 0), HH - 1) * WW;
            float a = row[xl];
            float2 m = *(const float2*)&row[gx0];
            float d = row[xr];
            in_reg[c][r][0] = (rok && ml) ? a   : 0.f;
            in_reg[c][r][1] = rok         ? m.x : 0.f;
            in_reg[c][r][2] = rok         ? m.y : 0.f;
            in_reg[c][r][3] = (rok && mr) ? d   : 0.f;
        }
    }

    float hv0[16], hv1[16];
    #pragma unroll
    for (int o = 0; o < 16; o++) {
        float a0 = c_b1[o], a1 = a0;
        #pragma unroll
        for (int c = 0; c < 3; c++)
            #pragma unroll
            for (int r = 0; r < 3; r++)
                #pragma unroll
                for (int kx = 0; kx < 3; kx++) {
                    const float w = c_w1[o * 27 + (c * 3 + r) * 3 + kx];
                    a0 = fmaf(in_reg[c][r][kx],     w, a0);
                    a1 = fmaf(in_reg[c][r][kx + 1], w, a1);
                }
        hv0[o] = gelu_fast(a0);
        hv1[o] = gelu_fast(a1);
    }

    // pack 2 px x 16 ch = 32 halves = 64B contiguous at x' = gx0+1
    __half2 t[16];
    #pragma unroll
    for (int p = 0; p < 8; p++) {
        t[p]     = __floats2half2_rn(hv0[2 * p], hv0[2 * p + 1]);
        t[8 + p] = __floats2half2_rn(hv1[2 * p], hv1[2 * p + 1]);
    }
    __half* dst = g_h + (((size_t)b * HH + y) * XP + gx0 + 1) * 16;
    uint4* d4 = (uint4*)dst;
    d4[0] = ((uint4*)t)[0];
    d4[1] = ((uint4*)t)[1];
    d4[2] = ((uint4*)t)[2];
    d4[3] = ((uint4*)t)[3];

    // zero pad columns x'=0 and x'=513 for this row
    if (threadIdx.x == 0) {
        uint4 z = make_uint4(0, 0, 0, 0);
        uint4* zp = (uint4*)(g_h + (((size_t)b * HH + y) * XP) * 16);
        zp[0] = z; zp[1] = z;
    }
    if (threadIdx.x == 255) {
        uint4 z = make_uint4(0, 0, 0, 0);
        uint4* zp = (uint4*)(g_h + (((size_t)b * HH + y) * XP + 513) * 16);
        zp[0] = z; zp[1] = z;
    }
}

// ---------------- Kernel B: conv2 per tap + bilinear, no smem ---------------
// 64x8 tile, 2 px/thread; each warp = one image row (uniform row guard).
__global__ __launch_bounds__(256)
void deform_kernel(const float* __restrict__ pm25,
                   float* __restrict__ out) {
    const int tid = threadIdx.x;
    const int b   = blockIdx.z;
    const int ty0 = blockIdx.y * 8;
    const int tx0 = blockIdx.x * 64;
    const int py  = tid >> 5;             // 0..7
    const int px2 = (tid & 31) * 2;       // 0..62
    const int gy  = ty0 + py;
    const int gx0 = tx0 + px2;

    const __half* hb = g_h + (size_t)b * HH * XP * 16;
    const float* pimg = pm25 + (size_t)b * HWS;

    float out0 = 0.f, out1 = 0.f;
    #pragma unroll 1
    for (int k = 0; k < 9; k++) {
        float wk = c_wt[k];
        if (wk == 0.f) continue;          // block-uniform skip

        float dy0 = c_b2[2 * k],     dy1 = dy0;
        float dx0 = c_b2[2 * k + 1], dx1 = dx0;
        const int wbase_y = (2 * k) * 144;
        const int wbase_x = (2 * k + 1) * 144;

        #pragma unroll
        for (int ky = 0; ky < 3; ky++) {
            const int ry = gy - 1 + ky;
            if ((unsigned)ry >= HH) continue;   // warp-uniform (warp = one row)
            // x' = gx0 + j corresponds to global col gx0-1+j, j = 0..3
            const uint4* rp = (const uint4*)(hb + ((size_t)ry * XP + gx0) * 16);
            uint4 u[4][2];
            #pragma unroll
            for (int j = 0; j < 4; j++) {
                u[j][0] = rp[j * 2];
                u[j][1] = rp[j * 2 + 1];
            }
            #pragma unroll
            for (int ci = 0; ci < 16; ci++) {
                float f0, f1, f2, f3;
                {
                    const __half2* h0 = (const __half2*)&u[0];
                    const __half2* h1 = (const __half2*)&u[1];
                    const __half2* h2 = (const __half2*)&u[2];
                    const __half2* h3 = (const __half2*)&u[3];
                    const int p = ci >> 1;
                    if (ci & 1) {
                        f0 = __high2float(h0[p]); f1 = __high2float(h1[p]);
                        f2 = __high2float(h2[p]); f3 = __high2float(h3[p]);
                    } else {
                        f0 = __low2float(h0[p]);  f1 = __low2float(h1[p]);
                        f2 = __low2float(h2[p]);  f3 = __low2float(h3[p]);
                    }
                }
                const int wi = ci * 9 + ky * 3;
                float wy0 = c_w2[wbase_y + wi + 0];
                float wy1 = c_w2[wbase_y + wi + 1];
                float wy2 = c_w2[wbase_y + wi + 2];
                float wx0 = c_w2[wbase_x + wi + 0];
                float wx1 = c_w2[wbase_x + wi + 1];
                float wx2 = c_w2[wbase_x + wi + 2];
                dy0 = fmaf(f0, wy0, dy0); dy0 = fmaf(f1, wy1, dy0); dy0 = fmaf(f2, wy2, dy0);
                dy1 = fmaf(f1, wy0, dy1); dy1 = fmaf(f2, wy1, dy1); dy1 = fmaf(f3, wy2, dy1);
                dx0 = fmaf(f0, wx0, dx0); dx0 = fmaf(f1, wx1, dx0); dx0 = fmaf(f2, wx2, dx0);
                dx1 = fmaf(f1, wx0, dx1); dx1 = fmaf(f2, wx1, dx1); dx1 = fmaf(f3, wx2, dx1);
            }
        }

        const float kyo = (float)(k / 3 - 1);
        const float kxo = (float)(k % 3 - 1);
        #pragma unroll
        for (int px = 0; px < 2; px++) {
            float dyv = px ? dy1 : dy0;
            float dxv = px ? dx1 : dx0;
            float py_ = (float)gy + kyo + dyv;
            float px_ = (float)(gx0 + px) + kxo + dxv;
            float y0f = floorf(py_), x0f = floorf(px_);
            float wy = py_ - y0f, wx = px_ - x0f;
            int y0 = (int)y0f, x0 = (int)x0f;
            int y1 = y0 + 1,   x1 = x0 + 1;
            bool vy0 = (unsigned)y0 < HH, vy1 = (unsigned)y1 < HH;
            bool vx0 = (unsigned)x0 < WW, vx1 = (unsigned)x1 < WW;
            int yc0 = min(max(y0, 0), HH - 1), yc1 = min(max(y1, 0), HH - 1);
            int xc0 = min(max(x0, 0), WW - 1), xc1 = min(max(x1, 0), WW - 1);
            const float* r0 = pimg + yc0 * WW;
            const float* r1 = pimg + yc1 * WW;
            float v00 = (vy0 && vx0) ? r0[xc0] : 0.f;
            float v01 = (vy0 && vx1) ? r0[xc1] : 0.f;
            float v10 = (vy1 && vx0) ? r1[xc0] : 0.f;
            float v11 = (vy1 && vx1) ? r1[xc1] : 0.f;
            float samp = (1.f - wy) * (1.f - wx) * v00
                       + (1.f - wy) * wx         * v01
                       + wy         * (1.f - wx) * v10
                       + wy         * wx         * v11;
            if (px) out1 = fmaf(samp, wk, out1);
            else    out0 = fmaf(samp, wk, out0);
        }
    }

    *(float2*)&out[(size_t)b * HWS + (size_t)gy * WW + gx0] = make_float2(out0, out1);
}

extern "C" void kernel_launch(void* const* d_in, const int* in_sizes, int n_in,
                              void* d_out, int out_size) {
    const float* pm25 = (const float*)d_in[0];
    const float* wind = (const float*)d_in[1];
    const float* topo = (const float*)d_in[2];

    cudaMemcpyToSymbolAsync(c_w1, d_in[3], 432  * sizeof(float), 0, cudaMemcpyDeviceToDevice);
    cudaMemcpyToSymbolAsync(c_b1, d_in[4], 16   * sizeof(float), 0, cudaMemcpyDeviceToDevice);
    cudaMemcpyToSymbolAsync(c_w2, d_in[5], 2592 * sizeof(float), 0, cudaMemcpyDeviceToDevice);
    cudaMemcpyToSymbolAsync(c_b2, d_in[6], 18   * sizeof(float), 0, cudaMemcpyDeviceToDevice);
    cudaMemcpyToSymbolAsync(c_wt, d_in[7], 9    * sizeof(float), 0, cudaMemcpyDeviceToDevice);

    float* out = (float*)d_out;
    int B = in_sizes[0] / (HH * WW);

    dim3 gridA(1, HH, B);              // all batches, one launch
    conv1_gelu_kernel<<<gridA, 256>>>(wind, topo);

    dim3 gridB(WW / 64, HH / 8, B);    // all batches, one launch
    deform_kernel<<<gridB, 256>>>(pm25, out);
}